// round 5
// baseline (speedup 1.0000x reference)
#include <cuda_runtime.h>
#include <cuda_bf16.h>

// EdgeModel: out[e] = relu(concat(src,dest,ea,u[batch[e]]) @ W1 + b1) @ W2 + b2
// Shapes: E=8e6 edges, W1 [4,10], W2 [10,19]. Pure HBM-streaming problem.
// One thread per edge; results staged in shared for coalesced float4 stores.
// NOTE: harness materializes the int64 `batch` tensor as int32 on device
// (supported dtypes are float32/int32/bf16) — reading it as long long was
// the R2 out-of-bounds crash.

#define TPB 256
#define H1 10
#define H2 19
#define OUT_PER_BLK (TPB * H2)   // 4864 floats = 19456 bytes (divisible by 16)

__global__ __launch_bounds__(TPB) void edge_model_kernel(
    const float* __restrict__ src,
    const float* __restrict__ dest,
    const float* __restrict__ ea,
    const float* __restrict__ u,
    const int*   __restrict__ batch,   // int32 on device
    const float* __restrict__ W1,   // [4,10] row-major
    const float* __restrict__ b1,   // [10]
    const float* __restrict__ W2,   // [10,19] row-major
    const float* __restrict__ b2,   // [19]
    float* __restrict__ out,        // [E,19]
    int E)
{
    // 16B alignment required for the float4 copy-out.
    __shared__ __align__(16) float stage[OUT_PER_BLK];
    __shared__ float sW1[4 * H1];
    __shared__ float sb1[H1];
    __shared__ float sW2[H1 * H2];
    __shared__ float sb2[H2];

    const int t = threadIdx.x;

    // Cooperative weight load (259 floats total)
    if (t < 4 * H1)        sW1[t] = W1[t];
    if (t < H1)            sb1[t] = b1[t];
    if (t < H1 * H2)       sW2[t] = W2[t];
    else if (t >= 224 && t < 224 + H2) sb2[t - 224] = b2[t - 224];
    __syncthreads();

    const long long base = (long long)blockIdx.x * TPB;
    const long long e = base + t;
    const int nvalid = (int)min((long long)TPB, (long long)E - base);

    if (t < nvalid) {
        const float s  = __ldg(&src[e]);
        const float d  = __ldg(&dest[e]);
        const float a  = __ldg(&ea[e]);
        const int   bi = __ldg(&batch[e]);
        const float ub = __ldg(&u[bi]);

        float h[H1];
        #pragma unroll
        for (int j = 0; j < H1; j++) {
            float acc = sb1[j];
            acc = fmaf(s,  sW1[0 * H1 + j], acc);
            acc = fmaf(d,  sW1[1 * H1 + j], acc);
            acc = fmaf(a,  sW1[2 * H1 + j], acc);
            acc = fmaf(ub, sW1[3 * H1 + j], acc);
            h[j] = fmaxf(acc, 0.0f);
        }

        float* st = &stage[t * H2];
        #pragma unroll
        for (int n = 0; n < H2; n++) {
            float acc = sb2[n];
            #pragma unroll
            for (int j = 0; j < H1; j++)
                acc = fmaf(h[j], sW2[j * H2 + n], acc);
            st[n] = acc;
        }
    }
    __syncthreads();

    // Coalesced write-out of this block's [nvalid*19] floats.
    float* gout = out + base * H2;
    if (nvalid == TPB) {
        // Full block: 4864 floats = 1216 float4. Global base is 16B-aligned
        // (blockIdx * 19456 bytes), stage is force-aligned above.
        float4* g4 = (float4*)gout;
        const float4* s4 = (const float4*)stage;
        #pragma unroll
        for (int i = t; i < OUT_PER_BLK / 4; i += TPB)
            g4[i] = s4[i];
    } else {
        const int total = nvalid * H2;
        for (int i = t; i < total; i += TPB)
            gout[i] = stage[i];
    }
}

extern "C" void kernel_launch(void* const* d_in, const int* in_sizes, int n_in,
                              void* d_out, int out_size)
{
    const float* src   = (const float*)d_in[0];
    const float* dest  = (const float*)d_in[1];
    const float* ea    = (const float*)d_in[2];
    const float* u     = (const float*)d_in[3];
    const int*   batch = (const int*)d_in[4];
    const float* W1    = (const float*)d_in[5];
    const float* b1    = (const float*)d_in[6];
    const float* W2    = (const float*)d_in[7];
    const float* b2    = (const float*)d_in[8];
    float* out = (float*)d_out;

    const int E = in_sizes[0];
    const int blocks = (E + TPB - 1) / TPB;
    edge_model_kernel<<<blocks, TPB>>>(src, dest, ea, u, batch,
                                       W1, b1, W2, b2, out, E);
}

// round 7
// speedup vs baseline: 1.6424x; 1.6424x over previous
#include <cuda_runtime.h>
#include <cuda_bf16.h>

// EdgeModel: out[e] = relu(concat(src,dest,ea,u[batch[e]]) @ W1 + b1) @ W2 + b2
// E=8e6, W1 [4,10], W2 [10,19]. HBM-streaming problem; R4 showed the naive
// version is L1-pipe bound (90.6% L1, 31% DRAM) from per-edge weight LDS.
// R5: 4 edges/thread (amortize weight LDS 4x), LDS.128 on padded W2,
// conflict-free stride-19 STS staging, float4 coalesced copy-out.

#define TPB 128
#define EPT 4
#define EPB (TPB * EPT)          // 512 edges per block
#define H1 10
#define H2 19
#define STAGE_FLOATS (EPB * H2)  // 9728 floats = 38912 B (divisible by 16)

__global__ __launch_bounds__(TPB) void edge_model_kernel(
    const float* __restrict__ src,
    const float* __restrict__ dest,
    const float* __restrict__ ea,
    const float* __restrict__ u,
    const int*   __restrict__ batch,   // int32 on device
    const float* __restrict__ W1,      // [4,10] row-major
    const float* __restrict__ b1,      // [10]
    const float* __restrict__ W2,      // [10,19] row-major
    const float* __restrict__ b2,      // [19]
    float* __restrict__ out,           // [E,19]
    int E)
{
    __shared__ __align__(16) float stage[STAGE_FLOATS];
    __shared__ float sW1[4 * H1];
    __shared__ float sb1[H1];
    __shared__ __align__(16) float sW2p[H1 * 20];  // padded rows: [10][20]
    __shared__ __align__(16) float sb2p[20];

    const int t = threadIdx.x;

    // Weight load: W2 padded to 20-wide rows so &sW2p[j*20 + 4m] is 16B-aligned.
    for (int i = t; i < 4 * H1; i += TPB) sW1[i] = W1[i];
    if (t < H1) sb1[t] = b1[t];
    for (int i = t; i < H1 * 20; i += TPB) {
        int j = i / 20, n = i % 20;
        sW2p[i] = (n < H2) ? W2[j * H2 + n] : 0.0f;
    }
    if (t < 20) sb2p[t] = (t < H2) ? b2[t] : 0.0f;
    __syncthreads();

    const long long base = (long long)blockIdx.x * EPB;
    const int nvalid = (int)min((long long)EPB, (long long)E - base);

    if (nvalid == EPB) {
        // ---- full-block fast path: 4 edges per thread, strided by TPB ----
        float s[EPT], d[EPT], a[EPT], ub[EPT];
        #pragma unroll
        for (int k = 0; k < EPT; k++) {
            const long long e = base + t + k * TPB;
            s[k]  = __ldg(&src[e]);
            d[k]  = __ldg(&dest[e]);
            a[k]  = __ldg(&ea[e]);
            ub[k] = __ldg(&u[__ldg(&batch[e])]);
        }

        // Layer 1: each weight LDS feeds 4 edges' FMAs.
        float h[EPT][H1];
        #pragma unroll
        for (int j = 0; j < H1; j++) {
            const float w0 = sW1[0 * H1 + j];
            const float w1 = sW1[1 * H1 + j];
            const float w2 = sW1[2 * H1 + j];
            const float w3 = sW1[3 * H1 + j];
            const float bb = sb1[j];
            #pragma unroll
            for (int k = 0; k < EPT; k++) {
                float acc = fmaf(ub[k], w3,
                            fmaf(a[k],  w2,
                            fmaf(d[k],  w1,
                            fmaf(s[k],  w0, bb))));
                h[k][j] = fmaxf(acc, 0.0f);
            }
        }

        // Layer 2: n blocked by 4, W2 row chunks via LDS.128.
        #pragma unroll
        for (int n0 = 0; n0 < H2; n0 += 4) {
            const float4 bb4 = *(const float4*)&sb2p[n0];
            float acc[EPT][4];
            #pragma unroll
            for (int k = 0; k < EPT; k++) {
                acc[k][0] = bb4.x; acc[k][1] = bb4.y;
                acc[k][2] = bb4.z; acc[k][3] = bb4.w;
            }
            #pragma unroll
            for (int j = 0; j < H1; j++) {
                const float4 w4 = *(const float4*)&sW2p[j * 20 + n0];
                #pragma unroll
                for (int k = 0; k < EPT; k++) {
                    acc[k][0] = fmaf(h[k][j], w4.x, acc[k][0]);
                    acc[k][1] = fmaf(h[k][j], w4.y, acc[k][1]);
                    acc[k][2] = fmaf(h[k][j], w4.z, acc[k][2]);
                    acc[k][3] = fmaf(h[k][j], w4.w, acc[k][3]);
                }
            }
            // stride-19 STS across lanes: gcd(19,32)=1 -> conflict-free.
            #pragma unroll
            for (int k = 0; k < EPT; k++) {
                float* st = &stage[(k * TPB + t) * H2 + n0];
                #pragma unroll
                for (int m = 0; m < 4; m++)
                    if (n0 + m < H2) st[m] = acc[k][m];
            }
        }
    } else if (t < nvalid || true) {
        // ---- tail path: scalar per edge ----
        for (int k = 0; k < EPT; k++) {
            const int idx = t + k * TPB;
            if (idx >= nvalid) break;
            const long long e = base + idx;
            const float s  = __ldg(&src[e]);
            const float d  = __ldg(&dest[e]);
            const float a  = __ldg(&ea[e]);
            const float ub = __ldg(&u[__ldg(&batch[e])]);
            float h[H1];
            #pragma unroll
            for (int j = 0; j < H1; j++) {
                float acc = fmaf(ub, sW1[3 * H1 + j],
                            fmaf(a,  sW1[2 * H1 + j],
                            fmaf(d,  sW1[1 * H1 + j],
                            fmaf(s,  sW1[0 * H1 + j], sb1[j]))));
                h[j] = fmaxf(acc, 0.0f);
            }
            #pragma unroll
            for (int n = 0; n < H2; n++) {
                float acc = sb2p[n];
                #pragma unroll
                for (int j = 0; j < H1; j++)
                    acc = fmaf(h[j], sW2p[j * 20 + n], acc);
                stage[idx * H2 + n] = acc;
            }
        }
    }
    __syncthreads();

    // Coalesced write-out.
    float* gout = out + base * H2;
    if (nvalid == EPB) {
        // 9728 floats = 2432 float4; global base = blockIdx*38912 B (16B-aligned).
        float4* g4 = (float4*)gout;
        const float4* s4 = (const float4*)stage;
        #pragma unroll
        for (int i = t; i < STAGE_FLOATS / 4; i += TPB)
            g4[i] = s4[i];
    } else {
        const int total = nvalid * H2;
        for (int i = t; i < total; i += TPB)
            gout[i] = stage[i];
    }
}

extern "C" void kernel_launch(void* const* d_in, const int* in_sizes, int n_in,
                              void* d_out, int out_size)
{
    const float* src   = (const float*)d_in[0];
    const float* dest  = (const float*)d_in[1];
    const float* ea    = (const float*)d_in[2];
    const float* u     = (const float*)d_in[3];
    const int*   batch = (const int*)d_in[4];
    const float* W1    = (const float*)d_in[5];
    const float* b1    = (const float*)d_in[6];
    const float* W2    = (const float*)d_in[7];
    const float* b2    = (const float*)d_in[8];
    float* out = (float*)d_out;

    const int E = in_sizes[0];
    const int blocks = (E + EPB - 1) / EPB;
    edge_model_kernel<<<blocks, TPB>>>(src, dest, ea, u, batch,
                                       W1, b1, W2, b2, out, E);
}